// round 1
// baseline (speedup 1.0000x reference)
#include <cuda_runtime.h>

// NeuralODE: y_{n+1} = y_n + dt * ( tanh(y_n @ W1 + b1) @ W2 + b2 )
// 250 Euler steps (50 intervals x 5 substeps), snapshot every 5 steps.
// B=8192 rows, D=128, H=64. Persistent SMEM-resident tile kernel, fp32 FMA.

#define NB          8192
#define DD          128
#define HH          64
#define T_OUT       51
#define N_INTERVALS 50
#define N_SUB       5
#define DT_F        0.001f
#define ROWS        32
#define NTHREADS    128

__device__ __forceinline__ float tanh_fast(float x) {
    float y;
    asm("tanh.approx.f32 %0, %1;" : "=f"(y) : "f"(x));
    return y;
}

extern __shared__ float smem[];

__global__ __launch_bounds__(NTHREADS, 2)
void node_kernel(const float* __restrict__ x0,
                 const float* __restrict__ W1,
                 const float* __restrict__ b1,
                 const float* __restrict__ W2,
                 const float* __restrict__ b2,
                 float* __restrict__ out)
{
    // SMEM layout (floats): W1[128][64] | W2[64][128] | b1[64] | b2[128] | y[32][128] | h[32][64]
    float* sW1 = smem;                 // 8192
    float* sW2 = sW1 + DD * HH;        // 8192
    float* sb1 = sW2 + HH * DD;        // 64
    float* sb2 = sb1 + HH;             // 128
    float* sy  = sb2 + DD;             // 4096
    float* sh  = sy  + ROWS * DD;      // 2048

    const int tid = threadIdx.x;
    const int rowStart = blockIdx.x * ROWS;

    // ---- load weights/biases ----
    for (int i = tid; i < DD * HH; i += NTHREADS) sW1[i] = W1[i];
    for (int i = tid; i < HH * DD; i += NTHREADS) sW2[i] = W2[i];
    if (tid < HH) sb1[tid] = b1[tid];
    if (tid < DD) sb2[tid] = b2[tid];

    // ---- init y0 = x0[:, 0] (x0 row = 256 floats, take first 128) ; write t=0 output ----
    const float4* x4   = reinterpret_cast<const float4*>(x0);
    float4*       out4 = reinterpret_cast<float4*>(out);
    float4*       sy4  = reinterpret_cast<float4*>(sy);
    for (int i = tid; i < ROWS * (DD / 4); i += NTHREADS) {
        int r = i >> 5;           // DD/4 = 32 float4 per row
        int c = i & 31;
        float4 v = x4[(size_t)(rowStart + r) * 64 + c];   // b*256 floats = b*64 float4
        sy4[r * 32 + c] = v;
        out4[(size_t)(rowStart + r) * (T_OUT * 32) + c] = v;   // t = 0
    }
    __syncthreads();

    // thread tile mapping
    const int rg = tid >> 4;          // 0..7 row groups
    const int cg = tid & 15;          // 0..15 col groups
    const int r0 = rg * 4;            // 4 rows per thread
    const int c1 = cg * 4;            // GEMM1: 4 cols ; GEMM2: cols {c1..c1+3, c1+64..c1+67}

    for (int iv = 0; iv < N_INTERVALS; ++iv) {
        for (int s = 0; s < N_SUB; ++s) {
            // ================= GEMM1: h = tanh(y @ W1 + b1) =================
            float acc[4][4];
            #pragma unroll
            for (int i = 0; i < 4; ++i)
                #pragma unroll
                for (int j = 0; j < 4; ++j)
                    acc[i][j] = sb1[c1 + j];

            #pragma unroll 4
            for (int k = 0; k < DD; k += 4) {
                float a_s[4][4];
                float w_s[4][4];
                #pragma unroll
                for (int i = 0; i < 4; ++i) {
                    float4 av = *reinterpret_cast<const float4*>(&sy[(r0 + i) * DD + k]);
                    a_s[i][0] = av.x; a_s[i][1] = av.y; a_s[i][2] = av.z; a_s[i][3] = av.w;
                }
                #pragma unroll
                for (int kk = 0; kk < 4; ++kk) {
                    float4 wv = *reinterpret_cast<const float4*>(&sW1[(k + kk) * HH + c1]);
                    w_s[kk][0] = wv.x; w_s[kk][1] = wv.y; w_s[kk][2] = wv.z; w_s[kk][3] = wv.w;
                }
                #pragma unroll
                for (int i = 0; i < 4; ++i)
                    #pragma unroll
                    for (int kk = 0; kk < 4; ++kk)
                        #pragma unroll
                        for (int j = 0; j < 4; ++j)
                            acc[i][j] = fmaf(a_s[i][kk], w_s[kk][j], acc[i][j]);
            }

            #pragma unroll
            for (int i = 0; i < 4; ++i) {
                float4 hv;
                hv.x = tanh_fast(acc[i][0]);
                hv.y = tanh_fast(acc[i][1]);
                hv.z = tanh_fast(acc[i][2]);
                hv.w = tanh_fast(acc[i][3]);
                *reinterpret_cast<float4*>(&sh[(r0 + i) * HH + c1]) = hv;
            }
            __syncthreads();

            // ================= GEMM2: dy = h @ W2 + b2 ; y += dt*dy =================
            float acc2[4][8];
            #pragma unroll
            for (int i = 0; i < 4; ++i)
                #pragma unroll
                for (int j = 0; j < 4; ++j) {
                    acc2[i][j]     = sb2[c1 + j];
                    acc2[i][4 + j] = sb2[64 + c1 + j];
                }

            #pragma unroll 4
            for (int k = 0; k < HH; k += 4) {
                float a_s[4][4];
                float wA[4][4], wB[4][4];
                #pragma unroll
                for (int i = 0; i < 4; ++i) {
                    float4 av = *reinterpret_cast<const float4*>(&sh[(r0 + i) * HH + k]);
                    a_s[i][0] = av.x; a_s[i][1] = av.y; a_s[i][2] = av.z; a_s[i][3] = av.w;
                }
                #pragma unroll
                for (int kk = 0; kk < 4; ++kk) {
                    float4 w0 = *reinterpret_cast<const float4*>(&sW2[(k + kk) * DD + c1]);
                    float4 w1 = *reinterpret_cast<const float4*>(&sW2[(k + kk) * DD + 64 + c1]);
                    wA[kk][0] = w0.x; wA[kk][1] = w0.y; wA[kk][2] = w0.z; wA[kk][3] = w0.w;
                    wB[kk][0] = w1.x; wB[kk][1] = w1.y; wB[kk][2] = w1.z; wB[kk][3] = w1.w;
                }
                #pragma unroll
                for (int i = 0; i < 4; ++i)
                    #pragma unroll
                    for (int kk = 0; kk < 4; ++kk) {
                        #pragma unroll
                        for (int j = 0; j < 4; ++j)
                            acc2[i][j]     = fmaf(a_s[i][kk], wA[kk][j], acc2[i][j]);
                        #pragma unroll
                        for (int j = 0; j < 4; ++j)
                            acc2[i][4 + j] = fmaf(a_s[i][kk], wB[kk][j], acc2[i][4 + j]);
                    }
            }

            // epilogue: y += dt * dy ; snapshot on last substep of interval
            const bool do_out = (s == N_SUB - 1);
            #pragma unroll
            for (int i = 0; i < 4; ++i) {
                float* yrow = &sy[(r0 + i) * DD];
                float4 y0v = *reinterpret_cast<float4*>(&yrow[c1]);
                float4 y1v = *reinterpret_cast<float4*>(&yrow[64 + c1]);
                y0v.x = fmaf(DT_F, acc2[i][0], y0v.x);
                y0v.y = fmaf(DT_F, acc2[i][1], y0v.y);
                y0v.z = fmaf(DT_F, acc2[i][2], y0v.z);
                y0v.w = fmaf(DT_F, acc2[i][3], y0v.w);
                y1v.x = fmaf(DT_F, acc2[i][4], y1v.x);
                y1v.y = fmaf(DT_F, acc2[i][5], y1v.y);
                y1v.z = fmaf(DT_F, acc2[i][6], y1v.z);
                y1v.w = fmaf(DT_F, acc2[i][7], y1v.w);
                *reinterpret_cast<float4*>(&yrow[c1])      = y0v;
                *reinterpret_cast<float4*>(&yrow[64 + c1]) = y1v;
                if (do_out) {
                    size_t base = ((size_t)(rowStart + r0 + i) * T_OUT + (iv + 1)) * 32;
                    out4[base + cg]      = y0v;
                    out4[base + 16 + cg] = y1v;
                }
            }
            __syncthreads();
        }
    }
}

extern "C" void kernel_launch(void* const* d_in, const int* in_sizes, int n_in,
                              void* d_out, int out_size)
{
    const float* x0 = (const float*)d_in[0];
    // d_in[1] = t (fixed grid, unused)
    const float* W1 = (const float*)d_in[2];
    const float* b1 = (const float*)d_in[3];
    const float* W2 = (const float*)d_in[4];
    const float* b2 = (const float*)d_in[5];
    float* out = (float*)d_out;

    const int smem_bytes = (DD * HH + HH * DD + HH + DD + ROWS * DD + ROWS * HH) * (int)sizeof(float);
    cudaFuncSetAttribute(node_kernel, cudaFuncAttributeMaxDynamicSharedMemorySize, smem_bytes);

    node_kernel<<<NB / ROWS, NTHREADS, smem_bytes>>>(x0, W1, b1, W2, b2, out);
}

// round 12
// speedup vs baseline: 1.0026x; 1.0026x over previous
#include <cuda_runtime.h>

// NeuralODE persistent kernel: packed f32x2 FMA + LDS-optimized tiling.
// y_{n+1} = y_n + dt * ( tanh(y_n @ W1 + b1) @ W2 + b2 ), 250 steps, snapshot every 5.
// 128 blocks x 128 threads, 64 rows/block. GEMM1: 8x4 tile, k-paired f32x2
// (W1 transposed in smem). GEMM2: 8x8 tile, j-paired f32x2 (W2 natural layout).

#define NB     8192
#define DD     128
#define HH     64
#define T_OUT  51
#define N_INT  50
#define N_SUB  5
#define DT_F   0.001f
#define ROWS   64
#define NT     128

// padded row strides (floats): stride*4 mod 128 == 16 -> conflict-free for
// distance-1-row lane pairs and stride-1-row lane runs.
#define YS     132   // y row stride
#define HS     68    // h row stride
#define W1TS   132   // W1T row stride

typedef unsigned long long u64;

__device__ __forceinline__ u64 ffma2(u64 a, u64 b, u64 c) {
    u64 d;
    asm("fma.rn.f32x2 %0, %1, %2, %3;" : "=l"(d) : "l"(a), "l"(b), "l"(c));
    return d;
}
__device__ __forceinline__ u64 dup2(float x) {
    u64 d; asm("mov.b64 %0, {%1, %1};" : "=l"(d) : "f"(x)); return d;
}
__device__ __forceinline__ u64 pk2(float lo, float hi) {
    u64 d; asm("mov.b64 %0, {%1, %2};" : "=l"(d) : "f"(lo), "f"(hi)); return d;
}
__device__ __forceinline__ float2 un2(u64 v) {
    float lo, hi; asm("mov.b64 {%0, %1}, %2;" : "=f"(lo), "=f"(hi) : "l"(v));
    return make_float2(lo, hi);
}
__device__ __forceinline__ float tanh_fast(float x) {
    float y; asm("tanh.approx.f32 %0, %1;" : "=f"(y) : "f"(x)); return y;
}

extern __shared__ float smem[];

__global__ __launch_bounds__(NT, 1)
void node_kernel(const float* __restrict__ x0,
                 const float* __restrict__ W1,
                 const float* __restrict__ b1,
                 const float* __restrict__ W2,
                 const float* __restrict__ b2,
                 float* __restrict__ out)
{
    // SMEM (floats): W1T[64][132] | W2[64][128] | b1[64] | b2[128] | y[64][132] | h[64][68]
    float* sW1T = smem;                      // 8448
    float* sW2  = sW1T + HH * W1TS;          // 8192
    float* sb1  = sW2  + HH * DD;            // 64
    float* sb2  = sb1  + HH;                 // 128
    float* sy   = sb2  + DD;                 // 8448
    float* sh   = sy   + ROWS * YS;          // 4352

    const int tid = threadIdx.x;
    const int rowStart = blockIdx.x * ROWS;

    // ---- weights: W1 transposed into padded rows; W2 natural ----
    for (int idx = tid; idx < DD * HH; idx += NT) {
        int k = idx >> 6, c = idx & 63;          // W1[k][c]
        sW1T[c * W1TS + k] = W1[idx];
    }
    for (int idx = tid; idx < HH * DD; idx += NT) sW2[idx] = W2[idx];
    if (tid < HH) sb1[tid] = b1[tid];
    if (tid < DD) sb2[tid] = b2[tid];

    // ---- y0 = x0[:, 0] (first 128 of 256 floats per batch row) ; write t=0 ----
    const float4* x4 = reinterpret_cast<const float4*>(x0);
    float4*       o4 = reinterpret_cast<float4*>(out);
    for (int i = tid; i < ROWS * 32; i += NT) {
        int r = i >> 5, c4 = i & 31;
        float4 v = x4[(size_t)(rowStart + r) * 64 + c4];
        *reinterpret_cast<float4*>(&sy[r * YS + c4 * 4]) = v;
        o4[(size_t)(rowStart + r) * (T_OUT * 32) + c4] = v;
    }
    __syncthreads();

    // thread mapping: rg = tid>>4 in 0..7 -> rows {rg, rg+8, ..., rg+56}
    const int rg = tid >> 4;
    const int cg = tid & 15;
    const u64 dtp = dup2(DT_F);

    for (int iv = 0; iv < N_INT; ++iv) {
        for (int s = 0; s < N_SUB; ++s) {
            // ==== GEMM1: h = tanh(y @ W1 + b1), 8 rows x 4 cols, k-paired ====
            // cols c_j = cg + 16*j ; acc.lo accumulates even-k, acc.hi odd-k
            u64 acc[8][4];
            {
                float bj[4];
                #pragma unroll
                for (int j = 0; j < 4; ++j) bj[j] = sb1[cg + 16 * j];
                #pragma unroll
                for (int i = 0; i < 8; ++i)
                    #pragma unroll
                    for (int j = 0; j < 4; ++j)
                        acc[i][j] = pk2(bj[j], 0.0f);
            }

            #pragma unroll 2
            for (int k4 = 0; k4 < DD; k4 += 4) {
                u64 a0[8], a1[8];
                #pragma unroll
                for (int i = 0; i < 8; ++i) {
                    ulonglong2 av = *reinterpret_cast<const ulonglong2*>(
                        &sy[(rg + 8 * i) * YS + k4]);
                    a0[i] = av.x; a1[i] = av.y;
                }
                u64 w0[4], w1[4];
                #pragma unroll
                for (int j = 0; j < 4; ++j) {
                    ulonglong2 wv = *reinterpret_cast<const ulonglong2*>(
                        &sW1T[(cg + 16 * j) * W1TS + k4]);
                    w0[j] = wv.x; w1[j] = wv.y;
                }
                #pragma unroll
                for (int i = 0; i < 8; ++i)
                    #pragma unroll
                    for (int j = 0; j < 4; ++j) {
                        acc[i][j] = ffma2(a0[i], w0[j], acc[i][j]);
                        acc[i][j] = ffma2(a1[i], w1[j], acc[i][j]);
                    }
            }

            #pragma unroll
            for (int i = 0; i < 8; ++i)
                #pragma unroll
                for (int j = 0; j < 4; ++j) {
                    float2 p = un2(acc[i][j]);
                    sh[(rg + 8 * i) * HS + cg + 16 * j] = tanh_fast(p.x + p.y);
                }
            __syncthreads();

            // ==== GEMM2: dy = h @ W2 + b2, 8 rows x 8 cols, j-paired ====
            // cols {4cg..4cg+3} U {64+4cg..64+4cg+3} as 4 f32x2 pairs
            u64 acc2[8][4];
            {
                ulonglong2 bA = *reinterpret_cast<const ulonglong2*>(&sb2[4 * cg]);
                ulonglong2 bB = *reinterpret_cast<const ulonglong2*>(&sb2[64 + 4 * cg]);
                #pragma unroll
                for (int i = 0; i < 8; ++i) {
                    acc2[i][0] = bA.x; acc2[i][1] = bA.y;
                    acc2[i][2] = bB.x; acc2[i][3] = bB.y;
                }
            }

            #pragma unroll 2
            for (int k4 = 0; k4 < HH; k4 += 4) {
                float4 hv[8];
                #pragma unroll
                for (int i = 0; i < 8; ++i)
                    hv[i] = *reinterpret_cast<const float4*>(&sh[(rg + 8 * i) * HS + k4]);
                #pragma unroll
                for (int kk = 0; kk < 4; ++kk) {
                    ulonglong2 wA = *reinterpret_cast<const ulonglong2*>(
                        &sW2[(k4 + kk) * DD + 4 * cg]);
                    ulonglong2 wB = *reinterpret_cast<const ulonglong2*>(
                        &sW2[(k4 + kk) * DD + 64 + 4 * cg]);
                    #pragma unroll
                    for (int i = 0; i < 8; ++i) {
                        const float* hp = reinterpret_cast<const float*>(&hv[i]);
                        u64 ad = dup2(hp[kk]);
                        acc2[i][0] = ffma2(ad, wA.x, acc2[i][0]);
                        acc2[i][1] = ffma2(ad, wA.y, acc2[i][1]);
                        acc2[i][2] = ffma2(ad, wB.x, acc2[i][2]);
                        acc2[i][3] = ffma2(ad, wB.y, acc2[i][3]);
                    }
                }
            }

            // ==== epilogue: y += dt*dy ; snapshot on last substep ====
            const bool do_out = (s == N_SUB - 1);
            ulonglong2* oU = reinterpret_cast<ulonglong2*>(out);
            #pragma unroll
            for (int i = 0; i < 8; ++i) {
                int r = rg + 8 * i;
                ulonglong2 y0v = *reinterpret_cast<const ulonglong2*>(&sy[r * YS + 4 * cg]);
                ulonglong2 y1v = *reinterpret_cast<const ulonglong2*>(&sy[r * YS + 64 + 4 * cg]);
                y0v.x = ffma2(dtp, acc2[i][0], y0v.x);
                y0v.y = ffma2(dtp, acc2[i][1], y0v.y);
                y1v.x = ffma2(dtp, acc2[i][2], y1v.x);
                y1v.y = ffma2(dtp, acc2[i][3], y1v.y);
                *reinterpret_cast<ulonglong2*>(&sy[r * YS + 4 * cg]) = y0v;
                *reinterpret_cast<ulonglong2*>(&sy[r * YS + 64 + 4 * cg]) = y1v;
                if (do_out) {
                    // out row (b,t) = 128 floats = 32 x 16B units
                    size_t base = ((size_t)(rowStart + r) * T_OUT + (iv + 1)) * 32;
                    oU[base + cg]      = y0v;   // cols 4cg..4cg+3
                    oU[base + 16 + cg] = y1v;   // cols 64+4cg..64+4cg+3
                }
            }
            __syncthreads();
        }
    }
}

extern "C" void kernel_launch(void* const* d_in, const int* in_sizes, int n_in,
                              void* d_out, int out_size)
{
    const float* x0 = (const float*)d_in[0];
    // d_in[1] = t (fixed dt grid, unused)
    const float* W1 = (const float*)d_in[2];
    const float* b1 = (const float*)d_in[3];
    const float* W2 = (const float*)d_in[4];
    const float* b2 = (const float*)d_in[5];
    float* out = (float*)d_out;

    const int smem_floats = HH * W1TS + HH * DD + HH + DD + ROWS * YS + ROWS * HS;
    const int smem_bytes  = smem_floats * (int)sizeof(float);
    cudaFuncSetAttribute(node_kernel, cudaFuncAttributeMaxDynamicSharedMemorySize, smem_bytes);

    node_kernel<<<NB / ROWS, NT, smem_bytes>>>(x0, W1, b1, W2, b2, out);
}

// round 17
// speedup vs baseline: 1.0466x; 1.0438x over previous
#include <cuda_runtime.h>

// NeuralODE persistent kernel R13: packed f32x2 FMA, 256 threads/block for
// 2 warps/SMSP latency hiding. 128 blocks x 64 rows.
// GEMM1: 4x4 tile, k-paired f32x2 (W1 transposed in smem).
// GEMM2: 4x8 tile, j-paired f32x2 (W2 natural layout).

#define NB     8192
#define DD     128
#define HH     64
#define T_OUT  51
#define N_INT  50
#define N_SUB  5
#define DT_F   0.001f
#define ROWS   64
#define NT     256

// padded row strides (floats)
#define YS     132   // y row stride   (528 B ; mod 128 = 16)
#define HS     80    // h row stride   (320 B ; mod 128 = 64)
#define W1TS   132   // W1T row stride

typedef unsigned long long u64;

__device__ __forceinline__ u64 ffma2(u64 a, u64 b, u64 c) {
    u64 d;
    asm("fma.rn.f32x2 %0, %1, %2, %3;" : "=l"(d) : "l"(a), "l"(b), "l"(c));
    return d;
}
__device__ __forceinline__ u64 dup2(float x) {
    u64 d; asm("mov.b64 %0, {%1, %1};" : "=l"(d) : "f"(x)); return d;
}
__device__ __forceinline__ u64 pk2(float lo, float hi) {
    u64 d; asm("mov.b64 %0, {%1, %2};" : "=l"(d) : "f"(lo), "f"(hi)); return d;
}
__device__ __forceinline__ float2 un2(u64 v) {
    float lo, hi; asm("mov.b64 {%0, %1}, %2;" : "=f"(lo), "=f"(hi) : "l"(v));
    return make_float2(lo, hi);
}
__device__ __forceinline__ float tanh_fast(float x) {
    float y; asm("tanh.approx.f32 %0, %1;" : "=f"(y) : "f"(x)); return y;
}

extern __shared__ float smem[];

__global__ __launch_bounds__(NT, 1)
void node_kernel(const float* __restrict__ x0,
                 const float* __restrict__ W1,
                 const float* __restrict__ b1,
                 const float* __restrict__ W2,
                 const float* __restrict__ b2,
                 float* __restrict__ out)
{
    // SMEM (floats): W1T[64][132] | W2[64][128] | b1[64] | b2[128] | y[64][132] | h[64][80]
    float* sW1T = smem;                      // 8448
    float* sW2  = sW1T + HH * W1TS;          // 8192
    float* sb1  = sW2  + HH * DD;            // 64
    float* sb2  = sb1  + HH;                 // 128
    float* sy   = sb2  + DD;                 // 8448
    float* sh   = sy   + ROWS * YS;          // 5120

    const int tid = threadIdx.x;
    const int rowStart = blockIdx.x * ROWS;

    // ---- weights: W1 transposed into padded rows; W2 natural ----
    for (int idx = tid; idx < DD * HH; idx += NT) {
        int k = idx >> 6, c = idx & 63;          // W1[k][c]
        sW1T[c * W1TS + k] = W1[idx];
    }
    for (int idx = tid; idx < HH * DD; idx += NT) sW2[idx] = W2[idx];
    if (tid < HH) sb1[tid] = b1[tid];
    else if (tid >= 128 && tid < 256) sb2[tid - 128] = b2[tid - 128];

    // ---- y0 = x0[:, 0] (first 128 of 256 floats per batch row) ; write t=0 ----
    const float4* x4 = reinterpret_cast<const float4*>(x0);
    float4*       o4 = reinterpret_cast<float4*>(out);
    for (int i = tid; i < ROWS * 32; i += NT) {
        int r = i >> 5, c4 = i & 31;
        float4 v = x4[(size_t)(rowStart + r) * 64 + c4];
        *reinterpret_cast<float4*>(&sy[r * YS + c4 * 4]) = v;
        o4[(size_t)(rowStart + r) * (T_OUT * 32) + c4] = v;
    }
    __syncthreads();

    // thread mapping: rg = tid>>4 in 0..15 -> rows {rg, rg+16, rg+32, rg+48}
    // warp = 2 adjacent rgs x 16 cgs; padded strides keep phases conflict-free.
    const int rg = tid >> 4;
    const int cg = tid & 15;
    const u64 dtp = dup2(DT_F);

    for (int iv = 0; iv < N_INT; ++iv) {
        for (int s = 0; s < N_SUB; ++s) {
            // ==== GEMM1: h = tanh(y @ W1 + b1), 4 rows x 4 cols, k-paired ====
            // cols c_j = cg + 16*j ; acc.lo accumulates even-k, acc.hi odd-k
            u64 acc[4][4];
            {
                float bj[4];
                #pragma unroll
                for (int j = 0; j < 4; ++j) bj[j] = sb1[cg + 16 * j];
                #pragma unroll
                for (int i = 0; i < 4; ++i)
                    #pragma unroll
                    for (int j = 0; j < 4; ++j)
                        acc[i][j] = pk2(bj[j], 0.0f);
            }

            #pragma unroll 4
            for (int k4 = 0; k4 < DD; k4 += 4) {
                u64 a0[4], a1[4];
                #pragma unroll
                for (int i = 0; i < 4; ++i) {
                    ulonglong2 av = *reinterpret_cast<const ulonglong2*>(
                        &sy[(rg + 16 * i) * YS + k4]);
                    a0[i] = av.x; a1[i] = av.y;
                }
                u64 w0[4], w1[4];
                #pragma unroll
                for (int j = 0; j < 4; ++j) {
                    ulonglong2 wv = *reinterpret_cast<const ulonglong2*>(
                        &sW1T[(cg + 16 * j) * W1TS + k4]);
                    w0[j] = wv.x; w1[j] = wv.y;
                }
                #pragma unroll
                for (int i = 0; i < 4; ++i)
                    #pragma unroll
                    for (int j = 0; j < 4; ++j) {
                        acc[i][j] = ffma2(a0[i], w0[j], acc[i][j]);
                        acc[i][j] = ffma2(a1[i], w1[j], acc[i][j]);
                    }
            }

            #pragma unroll
            for (int i = 0; i < 4; ++i)
                #pragma unroll
                for (int j = 0; j < 4; ++j) {
                    float2 p = un2(acc[i][j]);
                    sh[(rg + 16 * i) * HS + cg + 16 * j] = tanh_fast(p.x + p.y);
                }
            __syncthreads();

            // ==== GEMM2: dy = h @ W2 + b2, 4 rows x 8 cols, j-paired ====
            // cols {4cg..4cg+3} U {64+4cg..64+4cg+3} as 4 f32x2 pairs
            u64 acc2[4][4];
            {
                ulonglong2 bA = *reinterpret_cast<const ulonglong2*>(&sb2[4 * cg]);
                ulonglong2 bB = *reinterpret_cast<const ulonglong2*>(&sb2[64 + 4 * cg]);
                #pragma unroll
                for (int i = 0; i < 4; ++i) {
                    acc2[i][0] = bA.x; acc2[i][1] = bA.y;
                    acc2[i][2] = bB.x; acc2[i][3] = bB.y;
                }
            }

            #pragma unroll 4
            for (int k4 = 0; k4 < HH; k4 += 4) {
                float4 hv[4];
                #pragma unroll
                for (int i = 0; i < 4; ++i)
                    hv[i] = *reinterpret_cast<const float4*>(&sh[(rg + 16 * i) * HS + k4]);
                #pragma unroll
                for (int kk = 0; kk < 4; ++kk) {
                    ulonglong2 wA = *reinterpret_cast<const ulonglong2*>(
                        &sW2[(k4 + kk) * DD + 4 * cg]);
                    ulonglong2 wB = *reinterpret_cast<const ulonglong2*>(
                        &sW2[(k4 + kk) * DD + 64 + 4 * cg]);
                    #pragma unroll
                    for (int i = 0; i < 4; ++i) {
                        const float* hp = reinterpret_cast<const float*>(&hv[i]);
                        u64 ad = dup2(hp[kk]);
                        acc2[i][0] = ffma2(ad, wA.x, acc2[i][0]);
                        acc2[i][1] = ffma2(ad, wA.y, acc2[i][1]);
                        acc2[i][2] = ffma2(ad, wB.x, acc2[i][2]);
                        acc2[i][3] = ffma2(ad, wB.y, acc2[i][3]);
                    }
                }
            }

            // ==== epilogue: y += dt*dy ; snapshot on last substep ====
            const bool do_out = (s == N_SUB - 1);
            ulonglong2* oU = reinterpret_cast<ulonglong2*>(out);
            #pragma unroll
            for (int i = 0; i < 4; ++i) {
                int r = rg + 16 * i;
                ulonglong2 y0v = *reinterpret_cast<const ulonglong2*>(&sy[r * YS + 4 * cg]);
                ulonglong2 y1v = *reinterpret_cast<const ulonglong2*>(&sy[r * YS + 64 + 4 * cg]);
                y0v.x = ffma2(dtp, acc2[i][0], y0v.x);
                y0v.y = ffma2(dtp, acc2[i][1], y0v.y);
                y1v.x = ffma2(dtp, acc2[i][2], y1v.x);
                y1v.y = ffma2(dtp, acc2[i][3], y1v.y);
                *reinterpret_cast<ulonglong2*>(&sy[r * YS + 4 * cg]) = y0v;
                *reinterpret_cast<ulonglong2*>(&sy[r * YS + 64 + 4 * cg]) = y1v;
                if (do_out) {
                    // out row (b,t) = 128 floats = 32 x 16B units
                    size_t base = ((size_t)(rowStart + r) * T_OUT + (iv + 1)) * 32;
                    oU[base + cg]      = y0v;   // cols 4cg..4cg+3
                    oU[base + 16 + cg] = y1v;   // cols 64+4cg..64+4cg+3
                }
            }
            __syncthreads();
        }
    }
}

extern "C" void kernel_launch(void* const* d_in, const int* in_sizes, int n_in,
                              void* d_out, int out_size)
{
    const float* x0 = (const float*)d_in[0];
    // d_in[1] = t (fixed dt grid, unused)
    const float* W1 = (const float*)d_in[2];
    const float* b1 = (const float*)d_in[3];
    const float* W2 = (const float*)d_in[4];
    const float* b2 = (const float*)d_in[5];
    float* out = (float*)d_out;

    const int smem_floats = HH * W1TS + HH * DD + HH + DD + ROWS * YS + ROWS * HS;
    const int smem_bytes  = smem_floats * (int)sizeof(float);
    cudaFuncSetAttribute(node_kernel, cudaFuncAttributeMaxDynamicSharedMemorySize, smem_bytes);

    node_kernel<<<NB / ROWS, NT, smem_bytes>>>(x0, W1, b1, W2, b2, out);
}